// round 1
// baseline (speedup 1.0000x reference)
#include <cuda_runtime.h>
#include <math.h>

#define NROWS 1024
#define DIM 256
#define NPID 100000
#define NCQ 50000
#define NTOT 150000
#define NCHUNK 1172            // ceil(150000/128) -> 1172*128 = 150016
#define NEG_BIG -3.0e30f

// ---------------- device scratch (no allocations allowed) ----------------
__device__ float g_x[NROWS * DIM];            // normalized inputs, 1MB
__device__ unsigned char g_bad[NCHUNK * 128]; // all-zero flags (lut cols 0..P-1, cq cols P..)
__device__ float g_pm[NROWS * NCHUNK];        // per (row, chunk) max
__device__ float g_ps[NROWS * NCHUNK];        // per (row, chunk) sum-exp
__device__ float g_ce[NROWS];
__device__ int g_doupd;

// ---------------- block reduce helpers (256 threads) ----------------
__device__ __forceinline__ float block_sum256(float v) {
    __shared__ float sh[8];
    __shared__ float res;
    int lane = threadIdx.x & 31, wid = threadIdx.x >> 5;
    __syncthreads();  // protect shared reuse across calls
#pragma unroll
    for (int o = 16; o > 0; o >>= 1) v += __shfl_xor_sync(0xffffffffu, v, o);
    if (lane == 0) sh[wid] = v;
    __syncthreads();
    if (threadIdx.x == 0) {
        float s = 0.f;
#pragma unroll
        for (int i = 0; i < 8; i++) s += sh[i];
        res = s;
    }
    __syncthreads();
    return res;
}

__device__ __forceinline__ float block_max256(float v) {
    __shared__ float sh[8];
    __shared__ float res;
    int lane = threadIdx.x & 31, wid = threadIdx.x >> 5;
    __syncthreads();
#pragma unroll
    for (int o = 16; o > 0; o >>= 1) v = fmaxf(v, __shfl_xor_sync(0xffffffffu, v, o));
    if (lane == 0) sh[wid] = v;
    __syncthreads();
    if (threadIdx.x == 0) {
        float s = sh[0];
#pragma unroll
        for (int i = 1; i < 8; i++) s = fmaxf(s, sh[i]);
        res = s;
    }
    __syncthreads();
    return res;
}

// ---------------- A: L2 normalize inputs -> g_x ----------------
__global__ void k_norm(const float* __restrict__ inp) {
    int n = blockIdx.x, t = threadIdx.x;  // 1024 blocks x 256 thr
    float v = inp[n * DIM + t];
    float ss = block_sum256(v * v);
    float inv = 1.f / fmaxf(sqrtf(ss), 1e-12f);
    g_x[n * DIM + t] = v * inv;
}

// ---------------- A2: update gate = mean(ious) < 0.2 ----------------
__global__ void k_flag(const float* __restrict__ ious) {
    float s = 0.f;
    for (int i = threadIdx.x; i < NROWS; i += 256) s += ious[i];
    float S = block_sum256(s);
    if (threadIdx.x == 0) g_doupd = (S / (float)NROWS < 0.2f) ? 1 : 0;
}

// ---------------- B: copy lut/cq -> out (+1 offset) and compute bad flags ----------------
__global__ void k_copybad(const float* __restrict__ lut, const float* __restrict__ cq,
                          float* __restrict__ out) {
    int row = blockIdx.x * 8 + (threadIdx.x >> 5);  // grid 18750 -> 150000 rows
    int lane = threadIdx.x & 31;
    const float* src;
    float* dst;
    if (row < NPID) {
        src = lut + (size_t)row * DIM;
        dst = out + 1 + (size_t)row * DIM;
    } else {
        src = cq + (size_t)(row - NPID) * DIM;
        dst = out + 1 + (size_t)NPID * DIM + (size_t)(row - NPID) * DIM;
    }
    float4 a = reinterpret_cast<const float4*>(src)[lane];
    float4 b = reinterpret_cast<const float4*>(src)[lane + 32];
    bool nz = (a.x != 0.f) | (a.y != 0.f) | (a.z != 0.f) | (a.w != 0.f) |
              (b.x != 0.f) | (b.y != 0.f) | (b.z != 0.f) | (b.w != 0.f);
    unsigned m = __ballot_sync(0xffffffffu, nz);
    if (lane == 0) g_bad[row] = (m == 0u) ? 1 : 0;
    // scalar stores (dst is only 4B aligned due to the +1 loss slot)
    int o = lane * 4;
    dst[o + 0] = a.x; dst[o + 1] = a.y; dst[o + 2] = a.z; dst[o + 3] = a.w;
    dst[128 + o + 0] = b.x; dst[128 + o + 1] = b.y; dst[128 + o + 2] = b.z; dst[128 + o + 3] = b.w;
}

// ---------------- C: tiled fp32 GEMM + per-chunk online softmax partials ----------------
// grid (NCHUNK, 8), block 256. Tile: 128 rows x 128 cols, 8x8 per thread.
__global__ void __launch_bounds__(256) k_gemm(const float* __restrict__ lut,
                                              const float* __restrict__ cq) {
    __shared__ float xs[16][128];
    __shared__ float ws[16][132];
    __shared__ float red_m[128][16];
    __shared__ float red_s[128][16];

    int t = threadIdx.x;
    int tx = t & 15, ty = t >> 4;
    int col0 = blockIdx.x * 128;
    int row0 = blockIdx.y * 128;

    float acc[8][8];
#pragma unroll
    for (int i = 0; i < 8; i++)
#pragma unroll
        for (int j = 0; j < 8; j++) acc[i][j] = 0.f;

    for (int kt = 0; kt < 16; kt++) {
        int k0 = kt * 16;
#pragma unroll
        for (int r = 0; r < 2; r++) {
            int idx = t + r * 256;
            int n = idx >> 2, k4 = idx & 3;
            float4 v = *reinterpret_cast<const float4*>(g_x + (size_t)(row0 + n) * DIM + k0 + k4 * 4);
            xs[k4 * 4 + 0][n] = v.x; xs[k4 * 4 + 1][n] = v.y;
            xs[k4 * 4 + 2][n] = v.z; xs[k4 * 4 + 3][n] = v.w;
        }
#pragma unroll
        for (int r = 0; r < 2; r++) {
            int idx = t + r * 256;
            int c = idx >> 2, k4 = idx & 3;
            int gc = col0 + c;
            float4 v;
            if (gc < NPID)
                v = *reinterpret_cast<const float4*>(lut + (size_t)gc * DIM + k0 + k4 * 4);
            else if (gc < NTOT)
                v = *reinterpret_cast<const float4*>(cq + (size_t)(gc - NPID) * DIM + k0 + k4 * 4);
            else
                v = make_float4(0.f, 0.f, 0.f, 0.f);
            ws[k4 * 4 + 0][c] = v.x; ws[k4 * 4 + 1][c] = v.y;
            ws[k4 * 4 + 2][c] = v.z; ws[k4 * 4 + 3][c] = v.w;
        }
        __syncthreads();
#pragma unroll
        for (int kk = 0; kk < 16; kk++) {
            float a[8], b[8];
            *reinterpret_cast<float4*>(&a[0]) = *reinterpret_cast<float4*>(&xs[kk][ty * 8]);
            *reinterpret_cast<float4*>(&a[4]) = *reinterpret_cast<float4*>(&xs[kk][ty * 8 + 4]);
            *reinterpret_cast<float4*>(&b[0]) = *reinterpret_cast<float4*>(&ws[kk][tx * 8]);
            *reinterpret_cast<float4*>(&b[4]) = *reinterpret_cast<float4*>(&ws[kk][tx * 8 + 4]);
#pragma unroll
            for (int i = 0; i < 8; i++)
#pragma unroll
                for (int j = 0; j < 8; j++) acc[i][j] = fmaf(a[i], b[j], acc[i][j]);
        }
        __syncthreads();
    }

    // masking + per-thread row partials over its 8 columns
    int cbase = col0 + tx * 8;
    unsigned char badv[8];
#pragma unroll
    for (int j = 0; j < 8; j++) {
        int gc = cbase + j;
        badv[j] = (gc < NTOT) ? g_bad[gc] : (unsigned char)2;
    }
#pragma unroll
    for (int i = 0; i < 8; i++) {
        float vals[8];
        float mi = NEG_BIG;
#pragma unroll
        for (int j = 0; j < 8; j++) {
            float v;
            if (badv[j] == 2) v = NEG_BIG;
            else if (badv[j]) v = -30.f;
            else v = 30.f * acc[i][j];
            vals[j] = v;
            mi = fmaxf(mi, v);
        }
        float si = 0.f;
#pragma unroll
        for (int j = 0; j < 8; j++) si += expf(vals[j] - mi);
        red_m[ty * 8 + i][tx] = mi;
        red_s[ty * 8 + i][tx] = si;
    }
    __syncthreads();
    if (t < 128) {
        float M = NEG_BIG, S = 0.f;
#pragma unroll
        for (int q = 0; q < 16; q++) M = fmaxf(M, red_m[t][q]);
#pragma unroll
        for (int q = 0; q < 16; q++) S += red_s[t][q] * expf(red_m[t][q] - M);
        size_t o = (size_t)(row0 + t) * NCHUNK + blockIdx.x;
        g_pm[o] = M;
        g_ps[o] = S;
    }
}

// ---------------- D: per-row logsumexp + CE ----------------
__global__ void k_lse(const int* __restrict__ label, const float* __restrict__ lut) {
    int n = blockIdx.x, t = threadIdx.x;
    size_t base = (size_t)n * NCHUNK;
    float m = NEG_BIG;
    for (int i = t; i < NCHUNK; i += 256) m = fmaxf(m, g_pm[base + i]);
    float M = block_max256(m);
    float s = 0.f;
    for (int i = t; i < NCHUNK; i += 256) s += g_ps[base + i] * expf(g_pm[base + i] - M);
    float S = block_sum256(s);

    int y = label[n];
    float ce = 0.f;
    if (y < NPID) {
        if (g_bad[y]) {
            // reference sets this sample's own logit to 1.0 (-> 30 after scale)
            float M2 = fmaxf(M, 30.f);
            float S2 = S * expf(M - M2) + expf(30.f - M2) - expf(-30.f - M2);
            ce = M2 + logf(S2) - 30.f;
        } else {
            float d = block_sum256(g_x[n * DIM + t] * lut[(size_t)y * DIM + t]);
            ce = M + logf(S) - 30.f * d;
        }
    }
    if (t == 0) g_ce[n] = ce;
}

// ---------------- F: deterministic loss reduce ----------------
__global__ void k_loss(float* __restrict__ out) {
    float s = 0.f;
    for (int i = threadIdx.x; i < NROWS; i += 256) s += g_ce[i];
    float S = block_sum256(s);
    if (threadIdx.x == 0) out[0] = S / (float)NROWS;
}

// ---------------- E: memory-bank update (parallel per-pid chains) ----------------
// Semantics of the reference scan (both passes run when mean(ious)<0.2):
//   stream = [pass1: samples 0..N-1 (a=0.5,b=0.5)] ++ [pass2: samples 0..N-1 (a=1-iou,b=iou)]
//   labeled: lut[y] = l2norm(a*lut[y] + b*x)     (sequential per pid -> independent chains)
//   unlabeled: cq[(head + rank) % NCQ] = x        (rank = position among unlabeled in stream)
__global__ void k_update(const int* __restrict__ label, const float* __restrict__ ious,
                         const int* __restrict__ header, const float* __restrict__ lut,
                         float* __restrict__ out) {
    if (!g_doupd) return;
    int i = blockIdx.x, t = threadIdx.x;
    __shared__ int slab[NROWS];
    for (int j = t; j < NROWS; j += 256) slab[j] = label[j];
    __syncthreads();
    int y = slab[i];

    if (y >= NPID) {
        // unlabeled: two circular-queue writes at analytically computed slots
        int rank = 0, u = 0;
        for (int j = 0; j < NROWS; j++) {
            bool ul = (slab[j] >= NPID);
            u += ul ? 1 : 0;
            rank += (ul && j < i) ? 1 : 0;
        }
        int head = header[0];
        float v = g_x[i * DIM + t];
        size_t cqbase = 1 + (size_t)NPID * DIM;
        long long p1 = ((long long)head + rank) % NCQ;
        long long p2 = ((long long)head + u + rank) % NCQ;
        out[cqbase + (size_t)p1 * DIM + t] = v;
        out[cqbase + (size_t)p2 * DIM + t] = v;
    } else {
        // leader of this pid processes the whole chain
        bool leader = true;
        for (int j = 0; j < i; j++)
            if (slab[j] == y) { leader = false; break; }
        if (!leader) return;
        float val = lut[(size_t)y * DIM + t];
        for (int pass = 0; pass < 2; pass++) {
            for (int j = 0; j < NROWS; j++) {
                if (slab[j] != y) continue;
                float a, b;
                if (pass == 0) { a = 0.5f; b = 0.5f; }
                else { float io = ious[j]; a = 1.f - io; b = io; }
                val = a * val + b * g_x[j * DIM + t];
                float ss = block_sum256(val * val);
                val = val / fmaxf(sqrtf(ss), 1e-12f);
            }
        }
        out[1 + (size_t)y * DIM + t] = val;
    }
}

// ---------------- launch ----------------
extern "C" void kernel_launch(void* const* d_in, const int* in_sizes, int n_in,
                              void* d_out, int out_size) {
    const float* inputs = (const float*)d_in[0];
    const int* label = (const int*)d_in[1];
    const float* ious = (const float*)d_in[2];
    const float* lut = (const float*)d_in[3];
    const float* cq = (const float*)d_in[4];
    const int* header = (const int*)d_in[5];
    float* out = (float*)d_out;

    k_norm<<<NROWS, 256>>>(inputs);
    k_flag<<<1, 256>>>(ious);
    k_copybad<<<18750, 256>>>(lut, cq, out);
    dim3 gc(NCHUNK, 8);
    k_gemm<<<gc, 256>>>(lut, cq);
    k_lse<<<NROWS, 256>>>(label, lut);
    k_loss<<<1, 256>>>(out);
    k_update<<<NROWS, 256>>>(label, ious, header, lut, out);
}

// round 3
// speedup vs baseline: 1.8809x; 1.8809x over previous
#include <cuda_runtime.h>
#include <cuda_bf16.h>
#include <math.h>
#include <stdint.h>

#define NROWS 1024
#define DIM 256
#define NPID 100000
#define NCQ 50000
#define NTOT 150000
#define NCHUNK 1172            // chunks of 128 W-rows; 1172*128 = 150016
#define NWPAD 150016
#define NEG_BIG -3.0e30f

// ---------------- device scratch ----------------
__device__ float g_x[NROWS * DIM];                   // normalized inputs fp32
__device__ unsigned int g_xhi[NROWS * 128];          // x hi bf16x2 words [row][128]
__device__ unsigned int g_xlo[NROWS * 128];          // x lo bf16x2 words
__device__ unsigned char g_bad[NWPAD];               // all-zero flags
__device__ unsigned int g_badbits[NCHUNK * 4];       // packed flags, 32 cols/word
__device__ unsigned int g_whi[(size_t)NWPAD * 128];  // W hi bf16x2 words [row][128]
__device__ unsigned int g_wlo[(size_t)NWPAD * 128];  // W lo bf16x2 words
__device__ float g_pm[(size_t)NCHUNK * NROWS];       // per (chunk, row) max
__device__ float g_ps[(size_t)NCHUNK * NROWS];       // per (chunk, row) sum-exp
__device__ float g_ce[NROWS];
__device__ int g_doupd;

// ---------------- PTX helpers ----------------
__device__ __forceinline__ uint32_t smem_u32(const void* p) {
    uint32_t a;
    asm("{ .reg .u64 t; cvta.to.shared.u64 t, %1; cvt.u32.u64 %0, t; }" : "=r"(a) : "l"(p));
    return a;
}

__device__ __forceinline__ void ldm_x4(uint32_t* r, uint32_t addr) {
    asm volatile("ldmatrix.sync.aligned.m8n8.x4.shared.b16 {%0,%1,%2,%3}, [%4];"
                 : "=r"(r[0]), "=r"(r[1]), "=r"(r[2]), "=r"(r[3]) : "r"(addr));
}
__device__ __forceinline__ void ldm_x2(uint32_t* r, uint32_t addr) {
    asm volatile("ldmatrix.sync.aligned.m8n8.x2.shared.b16 {%0,%1}, [%2];"
                 : "=r"(r[0]), "=r"(r[1]) : "r"(addr));
}
__device__ __forceinline__ void mma_bf16(float* c, const uint32_t* a, const uint32_t* b) {
    asm volatile(
        "mma.sync.aligned.m16n8k16.row.col.f32.bf16.bf16.f32 "
        "{%0,%1,%2,%3}, {%4,%5,%6,%7}, {%8,%9}, {%0,%1,%2,%3};"
        : "+f"(c[0]), "+f"(c[1]), "+f"(c[2]), "+f"(c[3])
        : "r"(a[0]), "r"(a[1]), "r"(a[2]), "r"(a[3]), "r"(b[0]), "r"(b[1]));
}

// ---------------- block reduce helpers (256 threads) ----------------
__device__ __forceinline__ float block_sum256(float v) {
    __shared__ float sh[8];
    __shared__ float res;
    int lane = threadIdx.x & 31, wid = threadIdx.x >> 5;
    __syncthreads();
#pragma unroll
    for (int o = 16; o > 0; o >>= 1) v += __shfl_xor_sync(0xffffffffu, v, o);
    if (lane == 0) sh[wid] = v;
    __syncthreads();
    if (threadIdx.x == 0) {
        float s = 0.f;
#pragma unroll
        for (int i = 0; i < 8; i++) s += sh[i];
        res = s;
    }
    __syncthreads();
    return res;
}
__device__ __forceinline__ float block_max256(float v) {
    __shared__ float sh[8];
    __shared__ float res;
    int lane = threadIdx.x & 31, wid = threadIdx.x >> 5;
    __syncthreads();
#pragma unroll
    for (int o = 16; o > 0; o >>= 1) v = fmaxf(v, __shfl_xor_sync(0xffffffffu, v, o));
    if (lane == 0) sh[wid] = v;
    __syncthreads();
    if (threadIdx.x == 0) {
        float s = sh[0];
#pragma unroll
        for (int i = 1; i < 8; i++) s = fmaxf(s, sh[i]);
        res = s;
    }
    __syncthreads();
    return res;
}

// ---------------- bf16 hi/lo split ----------------
__device__ __forceinline__ uint32_t pack_hi(float a, float b, uint32_t& lo) {
    __nv_bfloat16 ha = __float2bfloat16(a);
    __nv_bfloat16 hb = __float2bfloat16(b);
    __nv_bfloat16 la = __float2bfloat16(a - __bfloat162float(ha));
    __nv_bfloat16 lb = __float2bfloat16(b - __bfloat162float(hb));
    lo = (uint32_t)__bfloat16_as_ushort(la) | ((uint32_t)__bfloat16_as_ushort(lb) << 16);
    return (uint32_t)__bfloat16_as_ushort(ha) | ((uint32_t)__bfloat16_as_ushort(hb) << 16);
}

// ---------------- A: L2 normalize inputs -> g_x ----------------
__global__ void k_norm(const float* __restrict__ inp) {
    int n = blockIdx.x, t = threadIdx.x;
    float v = inp[n * DIM + t];
    float ss = block_sum256(v * v);
    float inv = 1.f / fmaxf(sqrtf(ss), 1e-12f);
    g_x[n * DIM + t] = v * inv;
}

// ---------------- A3: pack x into bf16 hi/lo ----------------
__global__ void k_xpack() {
    int r = blockIdx.x, t = threadIdx.x;  // 1024 x 128
    float2 v = *reinterpret_cast<const float2*>(g_x + r * DIM + t * 2);
    uint32_t lo;
    uint32_t hi = pack_hi(v.x, v.y, lo);
    g_xhi[r * 128 + t] = hi;
    g_xlo[r * 128 + t] = lo;
}

// ---------------- A2: update gate ----------------
__global__ void k_flag(const float* __restrict__ ious) {
    float s = 0.f;
    for (int i = threadIdx.x; i < NROWS; i += 256) s += ious[i];
    float S = block_sum256(s);
    if (threadIdx.x == 0) g_doupd = (S / (float)NROWS < 0.2f) ? 1 : 0;
}

// ---------------- B: copy lut/cq -> out, bad flags, bf16 hi/lo conversion ----------------
__global__ void k_copybad(const float* __restrict__ lut, const float* __restrict__ cq,
                          float* __restrict__ out) {
    int row = blockIdx.x * 8 + (threadIdx.x >> 5);  // grid 18752 -> 150016 rows
    int lane = threadIdx.x & 31;
    uint32_t* whirow = g_whi + (size_t)row * 128;
    uint32_t* wlorow = g_wlo + (size_t)row * 128;
    if (row >= NTOT) {
        ((uint2*)whirow)[lane] = make_uint2(0, 0);
        ((uint2*)whirow)[lane + 32] = make_uint2(0, 0);
        ((uint2*)wlorow)[lane] = make_uint2(0, 0);
        ((uint2*)wlorow)[lane + 32] = make_uint2(0, 0);
        if (lane == 0) g_bad[row] = 1;
        return;
    }
    const float* src;
    float* dst;
    if (row < NPID) {
        src = lut + (size_t)row * DIM;
        dst = out + 1 + (size_t)row * DIM;
    } else {
        src = cq + (size_t)(row - NPID) * DIM;
        dst = out + 1 + (size_t)NPID * DIM + (size_t)(row - NPID) * DIM;
    }
    float4 a = reinterpret_cast<const float4*>(src)[lane];
    float4 b = reinterpret_cast<const float4*>(src)[lane + 32];
    bool nz = (a.x != 0.f) | (a.y != 0.f) | (a.z != 0.f) | (a.w != 0.f) |
              (b.x != 0.f) | (b.y != 0.f) | (b.z != 0.f) | (b.w != 0.f);
    unsigned m = __ballot_sync(0xffffffffu, nz);
    if (lane == 0) g_bad[row] = (m == 0u) ? 1 : 0;
    uint32_t l0, l1, l2, l3;
    uint32_t h0 = pack_hi(a.x, a.y, l0);
    uint32_t h1 = pack_hi(a.z, a.w, l1);
    uint32_t h2 = pack_hi(b.x, b.y, l2);
    uint32_t h3 = pack_hi(b.z, b.w, l3);
    ((uint2*)whirow)[lane] = make_uint2(h0, h1);
    ((uint2*)whirow)[lane + 32] = make_uint2(h2, h3);
    ((uint2*)wlorow)[lane] = make_uint2(l0, l1);
    ((uint2*)wlorow)[lane + 32] = make_uint2(l2, l3);
    int o = lane * 4;
    dst[o + 0] = a.x; dst[o + 1] = a.y; dst[o + 2] = a.z; dst[o + 3] = a.w;
    dst[128 + o + 0] = b.x; dst[128 + o + 1] = b.y; dst[128 + o + 2] = b.z; dst[128 + o + 3] = b.w;
}

// ---------------- B2: pack bad flags into bitmasks ----------------
__global__ void k_badbits() {
    int n = blockIdx.x, t = threadIdx.x;  // NCHUNK x 128
    int col = n * 128 + t;
    unsigned char f = g_bad[col];
    unsigned mask = __ballot_sync(0xffffffffu, f != 0);
    if ((t & 31) == 0) g_badbits[n * 4 + (t >> 5)] = mask;
}

// ---------------- C: bf16x3 mma.sync GEMM + fused online-softmax partials ----------------
// grid (8 m-tiles, NCHUNK chunks); block 256 = 8 warps as 2(M) x 4(N); warp tile 64x32.
// K=256 in 8 slabs of 32; 3-stage cp.async pipeline.
// Stage layout (bytes): Ahi[128][40]b16 @0, Alo @10240, Bhi @20480, Blo @30720.
#define STAGE_BYTES 40960
#define GEMM_SMEM (3 * STAGE_BYTES)

__global__ void __launch_bounds__(256, 1) k_gemm_mma() {
    extern __shared__ char smem[];
    uint32_t sb = smem_u32(smem);
    int tid = threadIdx.x, lane = tid & 31, wid = tid >> 5;
    int wm = wid >> 2, wn = wid & 3;
    int m0 = blockIdx.x * 128;
    int chunk = blockIdx.y;
    int n0 = chunk * 128;

    float acc[4][4][4];
#pragma unroll
    for (int a = 0; a < 4; a++)
#pragma unroll
        for (int b = 0; b < 4; b++)
#pragma unroll
            for (int c = 0; c < 4; c++) acc[a][b][c] = 0.f;

    auto issue_stage = [&](int kt, int st) {
        if (kt < 8) {
            uint32_t sbase = sb + st * STAGE_BYTES;
#pragma unroll
            for (int j = 0; j < 8; j++) {
                int idx = tid + j * 256;              // 0..2047
                int c = idx & 3;                      // 16B chunk within row
                int r = (idx >> 2) & 127;             // row
                int h = (idx >> 9) & 1;               // hi/lo
                int ab = idx >> 10;                   // 0 = A(x), 1 = B(W)
                const uint32_t* src = ab
                    ? ((h ? g_wlo : g_whi) + (size_t)(n0 + r) * 128 + kt * 16 + c * 4)
                    : ((h ? g_xlo : g_xhi) + (size_t)(m0 + r) * 128 + kt * 16 + c * 4);
                uint32_t dst = sbase + (uint32_t)((ab * 2 + h) * 10240 + (r * 40 + c * 8) * 2);
                asm volatile("cp.async.cg.shared.global [%0], [%1], 16;" :: "r"(dst), "l"(src));
            }
        }
        asm volatile("cp.async.commit_group;" ::: "memory");
    };

    issue_stage(0, 0);
    issue_stage(1, 1);

    int a_row = lane & 15;
    int a_k = (lane >> 4) * 8;
    int b_row = lane & 7;
    int b_k = ((lane >> 3) & 1) * 8;

    for (int kt = 0; kt < 8; kt++) {
        asm volatile("cp.async.wait_group 1;" ::: "memory");
        __syncthreads();
        int st = kt % 3;
        uint32_t Ahi = sb + st * STAGE_BYTES;
        uint32_t Alo = Ahi + 10240;
        uint32_t Bhi = Ahi + 20480;
        uint32_t Blo = Ahi + 30720;
#pragma unroll
        for (int ks = 0; ks < 2; ks++) {
            uint32_t ah[4][4], al[4][4], bh[4][2], bl[4][2];
#pragma unroll
            for (int mi = 0; mi < 4; mi++) {
                uint32_t off = (uint32_t)(((wm * 64 + mi * 16 + a_row) * 40 + ks * 16 + a_k) * 2);
                ldm_x4(ah[mi], Ahi + off);
                ldm_x4(al[mi], Alo + off);
            }
#pragma unroll
            for (int ni = 0; ni < 4; ni++) {
                uint32_t off = (uint32_t)(((wn * 32 + ni * 8 + b_row) * 40 + ks * 16 + b_k) * 2);
                ldm_x2(bh[ni], Bhi + off);
                ldm_x2(bl[ni], Blo + off);
            }
#pragma unroll
            for (int mi = 0; mi < 4; mi++)
#pragma unroll
                for (int ni = 0; ni < 4; ni++) {
                    mma_bf16(acc[mi][ni], ah[mi], bh[ni]);
                    mma_bf16(acc[mi][ni], ah[mi], bl[ni]);
                    mma_bf16(acc[mi][ni], al[mi], bh[ni]);
                }
        }
        __syncthreads();
        issue_stage(kt + 2, (kt + 2) % 3);
    }
    __syncthreads();

    // ---- epilogue: bad-mask, scale, online-softmax partials ----
    float* red_m = (float*)smem;        // [128][4]
    float* red_s = red_m + 512;
    uint32_t bits = g_badbits[chunk * 4 + wn];
    int l4 = lane & 3;
#pragma unroll
    for (int mi = 0; mi < 4; mi++) {
#pragma unroll
        for (int h = 0; h < 2; h++) {
            float v[8];
            float m = NEG_BIG;
#pragma unroll
            for (int ni = 0; ni < 4; ni++) {
#pragma unroll
                for (int c = 0; c < 2; c++) {
                    int j = ni * 8 + 2 * l4 + c;
                    float d = acc[mi][ni][h * 2 + c];
                    float vv = ((bits >> j) & 1u) ? -30.f : 30.f * d;
                    int gcol = n0 + wn * 32 + j;
                    if (gcol >= NTOT) vv = NEG_BIG;
                    v[ni * 2 + c] = vv;
                    m = fmaxf(m, vv);
                }
            }
            float s = 0.f;
#pragma unroll
            for (int q = 0; q < 8; q++) s += __expf(v[q] - m);
#pragma unroll
            for (int o = 1; o <= 2; o <<= 1) {
                float mo = __shfl_xor_sync(0xffffffffu, m, o);
                float so = __shfl_xor_sync(0xffffffffu, s, o);
                float mn = fmaxf(m, mo);
                s = s * __expf(m - mn) + so * __expf(mo - mn);
                m = mn;
            }
            if (l4 == 0) {
                int row = wm * 64 + mi * 16 + h * 8 + (lane >> 2);
                red_m[row * 4 + wn] = m;
                red_s[row * 4 + wn] = s;
            }
        }
    }
    __syncthreads();
    if (tid < 128) {
        float M = red_m[tid * 4 + 0];
#pragma unroll
        for (int w = 1; w < 4; w++) M = fmaxf(M, red_m[tid * 4 + w]);
        float S = 0.f;
#pragma unroll
        for (int w = 0; w < 4; w++) S += red_s[tid * 4 + w] * __expf(red_m[tid * 4 + w] - M);
        size_t o = (size_t)chunk * NROWS + m0 + tid;
        g_pm[o] = M;
        g_ps[o] = S;
    }
}

// ---------------- D: per-row logsumexp + CE (chunk-major partials) ----------------
__global__ void k_lse(const int* __restrict__ label, const float* __restrict__ lut) {
    int n = blockIdx.x, t = threadIdx.x;
    float m = NEG_BIG;
    for (int i = t; i < NCHUNK; i += 256) m = fmaxf(m, g_pm[(size_t)i * NROWS + n]);
    float M = block_max256(m);
    float s = 0.f;
    for (int i = t; i < NCHUNK; i += 256)
        s += g_ps[(size_t)i * NROWS + n] * expf(g_pm[(size_t)i * NROWS + n] - M);
    float S = block_sum256(s);

    int y = label[n];
    float ce = 0.f;
    if (y < NPID) {
        if (g_bad[y]) {
            float M2 = fmaxf(M, 30.f);
            float S2 = S * expf(M - M2) + expf(30.f - M2) - expf(-30.f - M2);
            ce = M2 + logf(S2) - 30.f;
        } else {
            float d = block_sum256(g_x[n * DIM + t] * lut[(size_t)y * DIM + t]);
            ce = M + logf(S) - 30.f * d;
        }
    }
    if (t == 0) g_ce[n] = ce;
}

// ---------------- F: deterministic loss reduce ----------------
__global__ void k_loss(float* __restrict__ out) {
    float s = 0.f;
    for (int i = threadIdx.x; i < NROWS; i += 256) s += g_ce[i];
    float S = block_sum256(s);
    if (threadIdx.x == 0) out[0] = S / (float)NROWS;
}

// ---------------- E: memory-bank update (parallel per-pid chains) ----------------
__global__ void k_update(const int* __restrict__ label, const float* __restrict__ ious,
                         const int* __restrict__ header, const float* __restrict__ lut,
                         float* __restrict__ out) {
    if (!g_doupd) return;
    int i = blockIdx.x, t = threadIdx.x;
    __shared__ int slab[NROWS];
    for (int j = t; j < NROWS; j += 256) slab[j] = label[j];
    __syncthreads();
    int y = slab[i];

    if (y >= NPID) {
        int rank = 0, u = 0;
        for (int j = 0; j < NROWS; j++) {
            bool ul = (slab[j] >= NPID);
            u += ul ? 1 : 0;
            rank += (ul && j < i) ? 1 : 0;
        }
        int head = header[0];
        float v = g_x[i * DIM + t];
        size_t cqbase = 1 + (size_t)NPID * DIM;
        long long p1 = ((long long)head + rank) % NCQ;
        long long p2 = ((long long)head + u + rank) % NCQ;
        out[cqbase + (size_t)p1 * DIM + t] = v;
        out[cqbase + (size_t)p2 * DIM + t] = v;
    } else {
        bool leader = true;
        for (int j = 0; j < i; j++)
            if (slab[j] == y) { leader = false; break; }
        if (!leader) return;
        float val = lut[(size_t)y * DIM + t];
        for (int pass = 0; pass < 2; pass++) {
            for (int j = 0; j < NROWS; j++) {
                if (slab[j] != y) continue;
                float a, b;
                if (pass == 0) { a = 0.5f; b = 0.5f; }
                else { float io = ious[j]; a = 1.f - io; b = io; }
                val = a * val + b * g_x[j * DIM + t];
                float ss = block_sum256(val * val);
                val = val / fmaxf(sqrtf(ss), 1e-12f);
            }
        }
        out[1 + (size_t)y * DIM + t] = val;
    }
}

// ---------------- launch ----------------
extern "C" void kernel_launch(void* const* d_in, const int* in_sizes, int n_in,
                              void* d_out, int out_size) {
    const float* inputs = (const float*)d_in[0];
    const int* label = (const int*)d_in[1];
    const float* ious = (const float*)d_in[2];
    const float* lut = (const float*)d_in[3];
    const float* cq = (const float*)d_in[4];
    const int* header = (const int*)d_in[5];
    float* out = (float*)d_out;

    cudaFuncSetAttribute(k_gemm_mma, cudaFuncAttributeMaxDynamicSharedMemorySize, GEMM_SMEM);

    k_norm<<<NROWS, 256>>>(inputs);
    k_xpack<<<NROWS, 128>>>();
    k_flag<<<1, 256>>>(ious);
    k_copybad<<<18752, 256>>>(lut, cq, out);
    k_badbits<<<NCHUNK, 128>>>();
    dim3 gg(8, NCHUNK);
    k_gemm_mma<<<gg, 256, GEMM_SMEM>>>();
    k_lse<<<NROWS, 256>>>(label, lut);
    k_loss<<<1, 256>>>(out);
    k_update<<<NROWS, 256>>>(label, ious, header, lut, out);
}

// round 4
// speedup vs baseline: 2.4569x; 1.3062x over previous
#include <cuda_runtime.h>
#include <cuda_bf16.h>
#include <math.h>
#include <stdint.h>

#define NROWS 1024
#define DIM 256
#define NPID 100000
#define NCQ 50000
#define NTOT 150000
#define NCHUNK 1172            // chunks of 128 W-rows; 1172*128 = 150016
#define NWPAD 150016
#define NEG_BIG -3.0e30f

// ---------------- device scratch ----------------
__device__ float g_x[NROWS * DIM];                      // normalized inputs fp32
__device__ float g_sx[NROWS];                           // per-x-row maxabs
__device__ float g_sw[NWPAD];                           // per-W-row maxabs
__device__ __align__(16) unsigned int g_xh[NROWS * 64]; // x hi s8 packed (4/word)
__device__ __align__(16) unsigned int g_xl[NROWS * 64]; // x lo s8 packed
__device__ __align__(16) unsigned int g_wh[(size_t)NWPAD * 64]; // W hi s8
__device__ __align__(16) unsigned int g_wl[(size_t)NWPAD * 64]; // W lo s8
__device__ unsigned char g_bad[NWPAD];                  // all-zero flags
__device__ unsigned int g_badbits[NCHUNK * 4];          // packed flags
__device__ float g_pm[(size_t)NCHUNK * NROWS];          // per (chunk, row) max
__device__ float g_ps[(size_t)NCHUNK * NROWS];          // per (chunk, row) sum-exp
__device__ float g_ce[NROWS];
__device__ int g_doupd;

// ---------------- PTX helpers ----------------
__device__ __forceinline__ uint32_t smem_u32(const void* p) {
    uint32_t a;
    asm("{ .reg .u64 t; cvta.to.shared.u64 t, %1; cvt.u32.u64 %0, t; }" : "=r"(a) : "l"(p));
    return a;
}
__device__ __forceinline__ void ldm_x4(uint32_t* r, uint32_t addr) {
    asm volatile("ldmatrix.sync.aligned.m8n8.x4.shared.b16 {%0,%1,%2,%3}, [%4];"
                 : "=r"(r[0]), "=r"(r[1]), "=r"(r[2]), "=r"(r[3]) : "r"(addr));
}
__device__ __forceinline__ void mma_s8(int* c, const uint32_t* a, const uint32_t* b) {
    asm volatile(
        "mma.sync.aligned.m16n8k32.row.col.s32.s8.s8.s32 "
        "{%0,%1,%2,%3}, {%4,%5,%6,%7}, {%8,%9}, {%0,%1,%2,%3};"
        : "+r"(c[0]), "+r"(c[1]), "+r"(c[2]), "+r"(c[3])
        : "r"(a[0]), "r"(a[1]), "r"(a[2]), "r"(a[3]), "r"(b[0]), "r"(b[1]));
}

// ---------------- block reduce helpers (256 threads) ----------------
__device__ __forceinline__ float block_sum256(float v) {
    __shared__ float sh[8];
    __shared__ float res;
    int lane = threadIdx.x & 31, wid = threadIdx.x >> 5;
    __syncthreads();
#pragma unroll
    for (int o = 16; o > 0; o >>= 1) v += __shfl_xor_sync(0xffffffffu, v, o);
    if (lane == 0) sh[wid] = v;
    __syncthreads();
    if (threadIdx.x == 0) {
        float s = 0.f;
#pragma unroll
        for (int i = 0; i < 8; i++) s += sh[i];
        res = s;
    }
    __syncthreads();
    return res;
}
__device__ __forceinline__ float block_max256(float v) {
    __shared__ float sh[8];
    __shared__ float res;
    int lane = threadIdx.x & 31, wid = threadIdx.x >> 5;
    __syncthreads();
#pragma unroll
    for (int o = 16; o > 0; o >>= 1) v = fmaxf(v, __shfl_xor_sync(0xffffffffu, v, o));
    if (lane == 0) sh[wid] = v;
    __syncthreads();
    if (threadIdx.x == 0) {
        float s = sh[0];
#pragma unroll
        for (int i = 1; i < 8; i++) s = fmaxf(s, sh[i]);
        res = s;
    }
    __syncthreads();
    return res;
}

// ---------------- s8 hi/lo quantization ----------------
__device__ __forceinline__ void quant2(float v, float qs, int& h, int& l) {
    float s = v * qs;
    float hf = rintf(s);
    h = (int)hf;
    l = (int)rintf((s - hf) * 254.f);
}
__device__ __forceinline__ void pack8(const float* v, float qs, uint32_t& hw, uint32_t& lw) {
    int h0, l0, h1, l1, h2, l2, h3, l3;
    quant2(v[0], qs, h0, l0);
    quant2(v[1], qs, h1, l1);
    quant2(v[2], qs, h2, l2);
    quant2(v[3], qs, h3, l3);
    hw = (uint32_t)(h0 & 255) | ((uint32_t)(h1 & 255) << 8) |
         ((uint32_t)(h2 & 255) << 16) | ((uint32_t)(h3 & 255) << 24);
    lw = (uint32_t)(l0 & 255) | ((uint32_t)(l1 & 255) << 8) |
         ((uint32_t)(l2 & 255) << 16) | ((uint32_t)(l3 & 255) << 24);
}

// ---------------- A: L2 normalize inputs -> g_x, row maxabs -> g_sx ----------------
__global__ void k_norm(const float* __restrict__ inp) {
    int n = blockIdx.x, t = threadIdx.x;
    float v = inp[n * DIM + t];
    float ss = block_sum256(v * v);
    float inv = 1.f / fmaxf(sqrtf(ss), 1e-12f);
    float xn = v * inv;
    g_x[n * DIM + t] = xn;
    float mx = block_max256(fabsf(xn));
    if (t == 0) g_sx[n] = mx;
}

// ---------------- A3: quantize x into s8 hi/lo ----------------
__global__ void k_xpack() {
    int r = blockIdx.x, t = threadIdx.x;  // 1024 x 64
    float4 v = *reinterpret_cast<const float4*>(g_x + r * DIM + t * 4);
    float sx = g_sx[r];
    float qs = sx > 0.f ? 127.f / sx : 0.f;
    float va[4] = {v.x, v.y, v.z, v.w};
    uint32_t hw, lw;
    pack8(va, qs, hw, lw);
    g_xh[r * 64 + t] = hw;
    g_xl[r * 64 + t] = lw;
}

// ---------------- A2: update gate ----------------
__global__ void k_flag(const float* __restrict__ ious) {
    float s = 0.f;
    for (int i = threadIdx.x; i < NROWS; i += 256) s += ious[i];
    float S = block_sum256(s);
    if (threadIdx.x == 0) g_doupd = (S / (float)NROWS < 0.2f) ? 1 : 0;
}

// ---------------- B: copy lut/cq -> out, bad flags, s8 quantization ----------------
__global__ void k_copybad(const float* __restrict__ lut, const float* __restrict__ cq,
                          float* __restrict__ out) {
    int row = blockIdx.x * 8 + (threadIdx.x >> 5);  // grid 18752 -> 150016 rows
    int lane = threadIdx.x & 31;
    uint32_t* whr = g_wh + (size_t)row * 64;
    uint32_t* wlr = g_wl + (size_t)row * 64;
    if (row >= NTOT) {
        whr[lane] = 0; whr[lane + 32] = 0;
        wlr[lane] = 0; wlr[lane + 32] = 0;
        if (lane == 0) { g_bad[row] = 1; g_sw[row] = 0.f; }
        return;
    }
    const float* src;
    float* dst;
    if (row < NPID) {
        src = lut + (size_t)row * DIM;
        dst = out + 1 + (size_t)row * DIM;
    } else {
        src = cq + (size_t)(row - NPID) * DIM;
        dst = out + 1 + (size_t)NPID * DIM + (size_t)(row - NPID) * DIM;
    }
    float4 a = reinterpret_cast<const float4*>(src)[lane];
    float4 b = reinterpret_cast<const float4*>(src)[lane + 32];
    float m = fmaxf(fmaxf(fmaxf(fabsf(a.x), fabsf(a.y)), fmaxf(fabsf(a.z), fabsf(a.w))),
                    fmaxf(fmaxf(fabsf(b.x), fabsf(b.y)), fmaxf(fabsf(b.z), fabsf(b.w))));
#pragma unroll
    for (int o = 16; o > 0; o >>= 1) m = fmaxf(m, __shfl_xor_sync(0xffffffffu, m, o));
    if (lane == 0) {
        g_bad[row] = (m == 0.f) ? 1 : 0;
        g_sw[row] = m;
    }
    float qs = m > 0.f ? 127.f / m : 0.f;
    float va[4] = {a.x, a.y, a.z, a.w}, vb[4] = {b.x, b.y, b.z, b.w};
    uint32_t hw, lw;
    pack8(va, qs, hw, lw);
    whr[lane] = hw; wlr[lane] = lw;
    pack8(vb, qs, hw, lw);
    whr[lane + 32] = hw; wlr[lane + 32] = lw;
    // copy to out (scalar: dst only 4B aligned due to +1 loss slot)
    int o = lane * 4;
    dst[o + 0] = a.x; dst[o + 1] = a.y; dst[o + 2] = a.z; dst[o + 3] = a.w;
    dst[128 + o + 0] = b.x; dst[128 + o + 1] = b.y; dst[128 + o + 2] = b.z; dst[128 + o + 3] = b.w;
}

// ---------------- B2: pack bad flags into bitmasks ----------------
__global__ void k_badbits() {
    int n = blockIdx.x, t = threadIdx.x;  // NCHUNK x 128
    int col = n * 128 + t;
    unsigned char f = g_bad[col];
    unsigned mask = __ballot_sync(0xffffffffu, f != 0);
    if ((t & 31) == 0) g_badbits[n * 4 + (t >> 5)] = mask;
}

// ---------------- C: s8x3 mma.sync GEMM + fused online-softmax partials ----------------
// grid (8 m-tiles, NCHUNK); block 512 = 16 warps (4m x 4n); warp tile 32x32.
// K = 256 in 8 slabs of 32 (one IMMA k32 per slab per frag); 3-stage cp.async ring.
// Stage layout: Ah[128][48B] @0, Al @6144, Bh @12288, Bl @18432 (stride 48: 16B-aligned,
// ldmatrix phase banks 12r mod 32 all distinct -> conflict-free).
#define STAGE_BYTES 24576
#define GEMM_SMEM (3 * STAGE_BYTES)

__global__ void __launch_bounds__(512, 1) k_gemm_i8() {
    extern __shared__ char smem[];
    uint32_t sb = smem_u32(smem);
    int tid = threadIdx.x, lane = tid & 31, wid = tid >> 5;
    int wm = wid >> 2, wn = wid & 3;
    int m0 = blockIdx.x * 128;
    int chunk = blockIdx.y;
    int n0 = chunk * 128;

    int acc1[2][4][4], acc2[2][4][4];
#pragma unroll
    for (int a = 0; a < 2; a++)
#pragma unroll
        for (int b = 0; b < 4; b++)
#pragma unroll
            for (int c = 0; c < 4; c++) { acc1[a][b][c] = 0; acc2[a][b][c] = 0; }

    auto issue_stage = [&](int kt, int st) {
        if (kt < 8) {
            uint32_t sbase = sb + st * STAGE_BYTES;
#pragma unroll
            for (int j = 0; j < 2; j++) {
                int idx = tid + j * 512;              // 0..1023
                int c = idx & 1;                      // 16B chunk within 32B slab-row
                int r = (idx >> 1) & 127;             // row
                int part = idx >> 8;                  // 0:Ah 1:Al 2:Bh 3:Bl
                const uint32_t* src;
                if (part == 0)      src = g_xh + (size_t)(m0 + r) * 64 + kt * 8 + c * 4;
                else if (part == 1) src = g_xl + (size_t)(m0 + r) * 64 + kt * 8 + c * 4;
                else if (part == 2) src = g_wh + (size_t)(n0 + r) * 64 + kt * 8 + c * 4;
                else                src = g_wl + (size_t)(n0 + r) * 64 + kt * 8 + c * 4;
                uint32_t dst = sbase + (uint32_t)(part * 6144 + r * 48 + c * 16);
                asm volatile("cp.async.cg.shared.global [%0], [%1], 16;" :: "r"(dst), "l"(src));
            }
        }
        asm volatile("cp.async.commit_group;" ::: "memory");
    };

    issue_stage(0, 0);
    issue_stage(1, 1);

    // ldmatrix lane addressing
    uint32_t a_r = (uint32_t)(lane & 15);
    uint32_t a_c = (uint32_t)((lane >> 4) * 16);
    uint32_t b_r = (uint32_t)((lane & 7) + ((lane >> 4) & 1) * 8);
    uint32_t b_c = (uint32_t)(((lane >> 3) & 1) * 16);

    for (int kt = 0; kt < 8; kt++) {
        asm volatile("cp.async.wait_group 1;" ::: "memory");
        __syncthreads();
        uint32_t Ah = sb + (uint32_t)((kt % 3) * STAGE_BYTES);
        uint32_t Al = Ah + 6144, Bh = Ah + 12288, Bl = Ah + 18432;

        uint32_t ah[2][4], al[2][4], bh[4][2], bl[4][2];
#pragma unroll
        for (int mi = 0; mi < 2; mi++) {
            uint32_t off = (uint32_t)((wm * 32 + mi * 16) + a_r) * 48 + a_c;
            ldm_x4(ah[mi], Ah + off);
            ldm_x4(al[mi], Al + off);
        }
#pragma unroll
        for (int p = 0; p < 2; p++) {
            uint32_t off = (uint32_t)((wn * 32 + p * 16) + b_r) * 48 + b_c;
            uint32_t t4[4];
            ldm_x4(t4, Bh + off);
            bh[p * 2][0] = t4[0]; bh[p * 2][1] = t4[1];
            bh[p * 2 + 1][0] = t4[2]; bh[p * 2 + 1][1] = t4[3];
            ldm_x4(t4, Bl + off);
            bl[p * 2][0] = t4[0]; bl[p * 2][1] = t4[1];
            bl[p * 2 + 1][0] = t4[2]; bl[p * 2 + 1][1] = t4[3];
        }
#pragma unroll
        for (int mi = 0; mi < 2; mi++)
#pragma unroll
            for (int ni = 0; ni < 4; ni++) {
                mma_s8(acc1[mi][ni], ah[mi], bh[ni]);
                mma_s8(acc2[mi][ni], ah[mi], bl[ni]);
                mma_s8(acc2[mi][ni], al[mi], bh[ni]);
            }
        __syncthreads();
        issue_stage(kt + 2, (kt + 2) % 3);
    }
    __syncthreads();

    // ---- epilogue: scale, bad-mask, online-softmax partials ----
    float* red_m = (float*)smem;  // [128][4]
    float* red_s = red_m + 512;
    uint32_t bits = g_badbits[chunk * 4 + wn];
    int l4 = lane & 3;
    float swc[8];
#pragma unroll
    for (int ni = 0; ni < 4; ni++)
#pragma unroll
        for (int c = 0; c < 2; c++)
            swc[ni * 2 + c] = g_sw[n0 + wn * 32 + ni * 8 + 2 * l4 + c];

#pragma unroll
    for (int mi = 0; mi < 2; mi++) {
#pragma unroll
        for (int h = 0; h < 2; h++) {
            int rloc = wm * 32 + mi * 16 + h * 8 + (lane >> 2);
            float sxv = g_sx[m0 + rloc] * (30.f / 16129.f);
            float v[8];
            float m = NEG_BIG;
#pragma unroll
            for (int ni = 0; ni < 4; ni++) {
#pragma unroll
                for (int c = 0; c < 2; c++) {
                    int ic = h * 2 + c;
                    float comb = (float)acc1[mi][ni][ic] +
                                 (float)acc2[mi][ni][ic] * (1.f / 254.f);
                    int j = ni * 8 + 2 * l4 + c;
                    float vv = ((bits >> j) & 1u) ? -30.f : comb * sxv * swc[ni * 2 + c];
                    if (n0 + wn * 32 + j >= NTOT) vv = NEG_BIG;
                    v[ni * 2 + c] = vv;
                    m = fmaxf(m, vv);
                }
            }
            float s = 0.f;
#pragma unroll
            for (int q = 0; q < 8; q++) s += __expf(v[q] - m);
#pragma unroll
            for (int o = 1; o <= 2; o <<= 1) {
                float mo = __shfl_xor_sync(0xffffffffu, m, o);
                float so = __shfl_xor_sync(0xffffffffu, s, o);
                float mn = fmaxf(m, mo);
                s = s * __expf(m - mn) + so * __expf(mo - mn);
                m = mn;
            }
            if (l4 == 0) {
                red_m[rloc * 4 + wn] = m;
                red_s[rloc * 4 + wn] = s;
            }
        }
    }
    __syncthreads();
    if (tid < 128) {
        float M = red_m[tid * 4 + 0];
#pragma unroll
        for (int w = 1; w < 4; w++) M = fmaxf(M, red_m[tid * 4 + w]);
        float S = 0.f;
#pragma unroll
        for (int w = 0; w < 4; w++) S += red_s[tid * 4 + w] * __expf(red_m[tid * 4 + w] - M);
        size_t o = (size_t)chunk * NROWS + m0 + tid;
        g_pm[o] = M;
        g_ps[o] = S;
    }
}

// ---------------- D: per-row logsumexp + CE ----------------
__global__ void k_lse(const int* __restrict__ label, const float* __restrict__ lut) {
    int n = blockIdx.x, t = threadIdx.x;
    float m = NEG_BIG;
    for (int i = t; i < NCHUNK; i += 256) m = fmaxf(m, g_pm[(size_t)i * NROWS + n]);
    float M = block_max256(m);
    float s = 0.f;
    for (int i = t; i < NCHUNK; i += 256)
        s += g_ps[(size_t)i * NROWS + n] * expf(g_pm[(size_t)i * NROWS + n] - M);
    float S = block_sum256(s);

    int y = label[n];
    float ce = 0.f;
    if (y < NPID) {
        if (g_bad[y]) {
            float M2 = fmaxf(M, 30.f);
            float S2 = S * expf(M - M2) + expf(30.f - M2) - expf(-30.f - M2);
            ce = M2 + logf(S2) - 30.f;
        } else {
            float d = block_sum256(g_x[n * DIM + t] * lut[(size_t)y * DIM + t]);
            ce = M + logf(S) - 30.f * d;
        }
    }
    if (t == 0) g_ce[n] = ce;
}

// ---------------- F: deterministic loss reduce ----------------
__global__ void k_loss(float* __restrict__ out) {
    float s = 0.f;
    for (int i = threadIdx.x; i < NROWS; i += 256) s += g_ce[i];
    float S = block_sum256(s);
    if (threadIdx.x == 0) out[0] = S / (float)NROWS;
}

// ---------------- E: memory-bank update (parallel per-pid chains) ----------------
__global__ void k_update(const int* __restrict__ label, const float* __restrict__ ious,
                         const int* __restrict__ header, const float* __restrict__ lut,
                         float* __restrict__ out) {
    if (!g_doupd) return;
    int i = blockIdx.x, t = threadIdx.x;
    __shared__ int slab[NROWS];
    for (int j = t; j < NROWS; j += 256) slab[j] = label[j];
    __syncthreads();
    int y = slab[i];

    if (y >= NPID) {
        int rank = 0, u = 0;
        for (int j = 0; j < NROWS; j++) {
            bool ul = (slab[j] >= NPID);
            u += ul ? 1 : 0;
            rank += (ul && j < i) ? 1 : 0;
        }
        int head = header[0];
        float v = g_x[i * DIM + t];
        size_t cqbase = 1 + (size_t)NPID * DIM;
        long long p1 = ((long long)head + rank) % NCQ;
        long long p2 = ((long long)head + u + rank) % NCQ;
        out[cqbase + (size_t)p1 * DIM + t] = v;
        out[cqbase + (size_t)p2 * DIM + t] = v;
    } else {
        bool leader = true;
        for (int j = 0; j < i; j++)
            if (slab[j] == y) { leader = false; break; }
        if (!leader) return;
        float val = lut[(size_t)y * DIM + t];
        for (int pass = 0; pass < 2; pass++) {
            for (int j = 0; j < NROWS; j++) {
                if (slab[j] != y) continue;
                float a, b;
                if (pass == 0) { a = 0.5f; b = 0.5f; }
                else { float io = ious[j]; a = 1.f - io; b = io; }
                val = a * val + b * g_x[j * DIM + t];
                float ss = block_sum256(val * val);
                val = val / fmaxf(sqrtf(ss), 1e-12f);
            }
        }
        out[1 + (size_t)y * DIM + t] = val;
    }
}

// ---------------- launch ----------------
extern "C" void kernel_launch(void* const* d_in, const int* in_sizes, int n_in,
                              void* d_out, int out_size) {
    const float* inputs = (const float*)d_in[0];
    const int* label = (const int*)d_in[1];
    const float* ious = (const float*)d_in[2];
    const float* lut = (const float*)d_in[3];
    const float* cq = (const float*)d_in[4];
    const int* header = (const int*)d_in[5];
    float* out = (float*)d_out;

    cudaFuncSetAttribute(k_gemm_i8, cudaFuncAttributeMaxDynamicSharedMemorySize, GEMM_SMEM);

    k_norm<<<NROWS, 256>>>(inputs);
    k_xpack<<<NROWS, 64>>>();
    k_flag<<<1, 256>>>(ious);
    k_copybad<<<18752, 256>>>(lut, cq, out);
    k_badbits<<<NCHUNK, 128>>>();
    dim3 gg(8, NCHUNK);
    k_gemm_i8<<<gg, 512, GEMM_SMEM>>>();
    k_lse<<<NROWS, 256>>>(label, lut);
    k_loss<<<1, 256>>>(out);
    k_update<<<NROWS, 256>>>(label, ious, header, lut, out);
}